// round 17
// baseline (speedup 1.0000x reference)
#include <cuda_runtime.h>
#include <cuda_fp16.h>
#include <cstdint>

// fp16 copies of the embedding tables (row = 128 halves = 256B = 16 uint4).
#define N_ROWS_MAX 100000
__device__ uint4 g_user_h[N_ROWS_MAX * 16];
__device__ uint4 g_item_h[N_ROWS_MAX * 16];

static __device__ __forceinline__ unsigned h2bits(__half2 h)
{
    return *reinterpret_cast<unsigned*>(&h);
}

// Wide streaming fp32 -> fp16: each thread reads 2 x float4 (32B, evict-first:
// fp32 source is single-use), writes 1 x uint4 (16B, default policy).
__global__ __launch_bounds__(256) void convert_f32_to_f16_kernel(
    const float4* __restrict__ src, uint4* __restrict__ dst, int n8)
{
    int i = blockIdx.x * blockDim.x + threadIdx.x;
    if (i >= n8) return;
    float4 v0 = __ldcs(&src[2 * i]);
    float4 v1 = __ldcs(&src[2 * i + 1]);
    uint4 o;
    o.x = h2bits(__floats2half2_rn(v0.x, v0.y));
    o.y = h2bits(__floats2half2_rn(v0.z, v0.w));
    o.z = h2bits(__floats2half2_rn(v1.x, v1.y));
    o.w = h2bits(__floats2half2_rn(v1.z, v1.w));
    dst[i] = o;
}

// 256-bit gather: one LDG.256 = 32B = 16 halves. 4 consecutive lanes x 32B
// = one fully-consumed 128B line per warp-instruction slot.
__device__ __forceinline__ void ldg256(const void* p, unsigned* r)
{
    asm("ld.global.nc.v8.b32 {%0,%1,%2,%3,%4,%5,%6,%7}, [%8];"
        : "=r"(r[0]), "=r"(r[1]), "=r"(r[2]), "=r"(r[3]),
          "=r"(r[4]), "=r"(r[5]), "=r"(r[6]), "=r"(r[7])
        : "l"(p));
}

// Accumulate dot of 8 fp16x2 word pairs into two fp32 chains.
__device__ __forceinline__ void acc32(const unsigned* aw, const unsigned* bw,
                                      float2& acc)
{
    #pragma unroll
    for (int i = 0; i < 8; i++) {
        __half2 ha = *reinterpret_cast<const __half2*>(&aw[i]);
        __half2 hb = *reinterpret_cast<const __half2*>(&bw[i]);
        float2 fa = __half22float2(ha);
        float2 fb = __half22float2(hb);
        acc.x = fmaf(fa.x, fb.x, acc.x);
        acc.y = fmaf(fa.y, fb.y, acc.y);
    }
}

// Scorer inner loop: 4 lanes per edge, 8 edges per warp. fp16 row = 256B =
// 8 x 32B chunks; lane covers chunks {sub, sub+4} of both rows ->
// 4 independent LDG.256 per thread, every wavefront a full 128B line,
// half the load-instruction count of the 16B-chunk shapes.
__device__ __forceinline__ float dot_rows256(const char* __restrict__ srow,
                                             const char* __restrict__ drow,
                                             int sub)
{
    unsigned a0[8], a1[8], b0[8], b1[8];
    ldg256(srow + sub * 32,        a0);
    ldg256(drow + sub * 32,        b0);
    ldg256(srow + (sub + 4) * 32,  a1);
    ldg256(drow + (sub + 4) * 32,  b1);

    float2 acc0 = make_float2(0.f, 0.f);
    float2 acc1 = make_float2(0.f, 0.f);
    acc32(a0, b0, acc0);
    acc32(a1, b1, acc1);
    return (acc0.x + acc0.y) + (acc1.x + acc1.y);
}

// Single-etype scorer (srcTab/dstTab passed explicitly; clean access stream).
__global__ __launch_bounds__(256) void edge_dot1_h_kernel(
    const uint4* __restrict__ srcTab, const int* __restrict__ si,
    const uint4* __restrict__ dstTab, const int* __restrict__ di,
    float* __restrict__ out, int E)
{
    const int lane = threadIdx.x & 31;
    const int wib = threadIdx.x >> 5;
    const int sub = lane & 3;
    const int group = lane >> 2;

    const int e = blockIdx.x * 64 + wib * 8 + group;
    if (e >= E) return;

    const int s_idx = __ldcs(&si[e]);
    const int d_idx = __ldcs(&di[e]);

    const char* srow = reinterpret_cast<const char*>(srcTab) + (size_t)s_idx * 256;
    const char* drow = reinterpret_cast<const char*>(dstTab) + (size_t)d_idx * 256;

    float sum = dot_rows256(srow, drow, sub);

    sum += __shfl_xor_sync(0xFFFFFFFFu, sum, 1);
    sum += __shfl_xor_sync(0xFFFFFFFFu, sum, 2);

    if (sub == 0) __stcs(&out[e], sum);
}

extern "C" void kernel_launch(void* const* d_in, const int* in_sizes, int n_in,
                              void* d_out, int out_size)
{
    const float* h_user = (const float*)d_in[0];
    const float* h_item = (const float*)d_in[1];
    const int* src_clicks    = (const int*)d_in[2];
    const int* dst_clicks    = (const int*)d_in[3];
    const int* src_clickedby = (const int*)d_in[4];
    const int* dst_clickedby = (const int*)d_in[5];
    const int* src_follows   = (const int*)d_in[6];
    const int* dst_follows   = (const int*)d_in[7];
    float* out = (float*)d_out;

    const int E = in_sizes[2];          // edges per etype (500000)

    static cudaStream_t s1 = nullptr;
    static cudaEvent_t ev_user = nullptr, ev_item = nullptr, ev_s1 = nullptr;
    if (!s1) {
        cudaStreamCreateWithFlags(&s1, cudaStreamNonBlocking);
        cudaEventCreateWithFlags(&ev_user, cudaEventDisableTiming);
        cudaEventCreateWithFlags(&ev_item, cudaEventDisableTiming);
        cudaEventCreateWithFlags(&ev_s1, cudaEventDisableTiming);
    }

    uint4* gu = nullptr; uint4* gi = nullptr;
    cudaGetSymbolAddress((void**)&gu, g_user_h);
    cudaGetSymbolAddress((void**)&gi, g_item_h);
    const int n8u = in_sizes[0] / 8;
    const int n8i = in_sizes[1] / 8;

    const int sblocks = (E + 63) / 64;  // 64 edges per block

    // origin: conv_user -> ev_user -> conv_item -> ev_item -> clicks -> wait s1
    // s1:     wait ev_user -> follows -> wait ev_item -> clickedby -> ev_s1
    convert_f32_to_f16_kernel<<<(n8u + 255) / 256, 256>>>(
        (const float4*)h_user, gu, n8u);
    cudaEventRecord(ev_user, 0);

    cudaStreamWaitEvent(s1, ev_user, 0);
    edge_dot1_h_kernel<<<sblocks, 256, 0, s1>>>(
        gu, src_follows, gu, dst_follows, out + 2 * (size_t)E, E);

    convert_f32_to_f16_kernel<<<(n8i + 255) / 256, 256>>>(
        (const float4*)h_item, gi, n8i);
    cudaEventRecord(ev_item, 0);

    cudaStreamWaitEvent(s1, ev_item, 0);
    edge_dot1_h_kernel<<<sblocks, 256, 0, s1>>>(
        gi, src_clickedby, gu, dst_clickedby, out + (size_t)E, E);
    cudaEventRecord(ev_s1, s1);

    edge_dot1_h_kernel<<<sblocks, 256>>>(
        gu, src_clicks, gi, dst_clicks, out, E);

    cudaStreamWaitEvent(0, ev_s1, 0);
}